// round 6
// baseline (speedup 1.0000x reference)
#include <cuda_runtime.h>

// MultiStageFIRFilter: y = x + sum_{a=1..20} xa_a,
//   xa_a[b,t] = (1/a) * sum_{k=0..24} mc[b,t,k] * xa_{a-1}[b,t-k]  (xa_0 = x, causal)
//
// Two-kernel stage split (10+10): halves the halo (480 -> 240 per kernel), so
// EXT drops 1024 -> 512 and total recompute falls 37%. 128 threads/block,
// R=4 positions/thread, 244 blocks/kernel -> 2 CTAs on most SMs whose
// barrier/load/FMA phases interleave. State between kernels in device scratch.

#define NB      4
#define NT      16384
#define M       25
#define THREADS 128
#define R       4
#define EXT     512       // THREADS * R
#define KSTAGES 10
#define KHALO   240       // KSTAGES * 24
#define TILE    272       // EXT - KHALO
#define PAD     24
#define NTILES  61        // 61 * 272 = 16592 >= 16384

__device__ float g_xa[NB][NT];   // xa_10
__device__ float g_y [NB][NT];   // x + sum_{a=1..10} xa_a

template<int PHASE>   // 0: stages 1..10 (x -> scratch), 1: stages 11..20 (scratch -> out)
__global__ __launch_bounds__(THREADS)
void fir_kernel(const float* __restrict__ x, const float* __restrict__ mc,
                float* __restrict__ out)
{
    __shared__ __align__(16) float s0[PAD + EXT];
    __shared__ __align__(16) float s1[PAD + EXT];

    const int tile = blockIdx.x % NTILES;
    const int b    = blockIdx.x / NTILES;
    const int t0   = tile * TILE;
    const int tid  = threadIdx.x;
    const int i0   = R * tid;              // local position (multiple of 4)
    const int p0   = t0 - KHALO + i0;      // global time of first position (mult of 4)
    const size_t rowbase = (size_t)b * NT;
    // p0 and NT are multiples of 4 -> the 4 rows are all-valid or all-invalid
    const bool valid = (p0 >= 0 && p0 + R - 1 < NT);

    if (tid < PAD) { s0[tid] = 0.0f; s1[tid] = 0.0f; }

    // ---- coefficients: c[25*r + k] = mc[p0+r][k]; contiguous row-major, 16B-aligned ----
    float c[100];
    if (valid) {
        const float4* g = (const float4*)(mc + (rowbase + (size_t)p0) * M);
        #pragma unroll
        for (int k = 0; k < 25; k++) {
            float4 v4 = g[k];
            c[4*k] = v4.x; c[4*k+1] = v4.y; c[4*k+2] = v4.z; c[4*k+3] = v4.w;
        }
    } else {
        #pragma unroll
        for (int j = 0; j < 100; j++) c[j] = 0.0f;   // invalid rows => acc == 0 exactly
    }

    // ---- initial state ----
    float v[R], y[R];
    if (valid) {
        const float4 xv = (PHASE == 0) ? *(const float4*)(x + rowbase + p0)
                                       : *(const float4*)(&g_xa[b][p0]);
        v[0] = xv.x; v[1] = xv.y; v[2] = xv.z; v[3] = xv.w;
        if (PHASE == 0) {
            #pragma unroll
            for (int r = 0; r < R; r++) y[r] = v[r];
        } else {
            const float4 yv = *(const float4*)(&g_y[b][p0]);
            y[0] = yv.x; y[1] = yv.y; y[2] = yv.z; y[3] = yv.w;
        }
    } else {
        #pragma unroll
        for (int r = 0; r < R; r++) { v[r] = 0.0f; y[r] = 0.0f; }
    }

    *((float4*)(s0 + PAD + i0)) = make_float4(v[0], v[1], v[2], v[3]);
    __syncthreads();

    float* cur = s0;
    float* nxt = s1;

    #pragma unroll
    for (int s = 1; s <= KSTAGES; s++) {
        const float inv = 1.0f / (float)(PHASE * KSTAGES + s);   // compile-time constant
        if (tid >= 6 * s) {                    // exactness trim: need local pos >= 24s
            // w24[j] = prev[position i0-24+j]; position q lives at smem index PAD+q,
            // so the window starts at cur + i0 (16B-aligned).
            float w24[24];
            const float4* wp = (const float4*)(cur + i0);
            #pragma unroll
            for (int j = 0; j < 6; j++) {
                float4 q = wp[j];
                w24[4*j] = q.x; w24[4*j+1] = q.y; w24[4*j+2] = q.z; w24[4*j+3] = q.w;
            }

            float acc[R];
            #pragma unroll
            for (int r = 0; r < R; r++) {
                float pA = 0.0f, pB = 0.0f;    // two independent chains per output
                #pragma unroll
                for (int k = 0; k <= 12; k++) {
                    const int d = r - k;
                    const float val = (d >= 0) ? v[d] : w24[24 + d];
                    pA = fmaf(c[25*r + k], val, pA);
                }
                #pragma unroll
                for (int k = 13; k <= 24; k++) {
                    pB = fmaf(c[25*r + k], w24[24 + r - k], pB);
                }
                acc[r] = (pA + pB) * inv;
            }
            #pragma unroll
            for (int r = 0; r < R; r++) { y[r] += acc[r]; v[r] = acc[r]; }
            *((float4*)(nxt + PAD + i0)) = make_float4(v[0], v[1], v[2], v[3]);
        }
        __syncthreads();
        float* tmp = cur; cur = nxt; nxt = tmp;
    }

    // ---- write owned (non-halo) results ----
    if (i0 >= KHALO && p0 < NT) {            // p0 >= t0 >= 0 here; rows all < NT (valid)
        if (PHASE == 0) {
            *((float4*)(&g_xa[b][p0])) = make_float4(v[0], v[1], v[2], v[3]);
            *((float4*)(&g_y [b][p0])) = make_float4(y[0], y[1], y[2], y[3]);
        } else {
            *((float4*)(out + rowbase + p0)) = make_float4(y[0], y[1], y[2], y[3]);
        }
    }
}

extern "C" void kernel_launch(void* const* d_in, const int* in_sizes, int n_in,
                              void* d_out, int out_size)
{
    const float* x  = (const float*)d_in[0];   // (4, 16384) float32
    const float* mc = (const float*)d_in[1];   // (4, 16384, 25) float32
    float* out = (float*)d_out;                // (4, 16384) float32
    fir_kernel<0><<<NB * NTILES, THREADS>>>(x, mc, out);
    fir_kernel<1><<<NB * NTILES, THREADS>>>(x, mc, out);
}